// round 17
// baseline (speedup 1.0000x reference)
// R17: f16-accumulator HMMA (K=64 f16 chain -> fp32 promote per k64 iter).
// Discriminates MAC-rate wall vs issue/RF-width wall on the sm_103a legacy pipe.
// Chassis = R13 (known-good); launch_bounds(256,1) for ~155 regs.
#include <cuda_runtime.h>
#include <cuda_fp16.h>
#include <cstdint>

#define BATCH 4
#define NSEQ  2048
#define DIM   512
#define HID   512
#define NEXP  16
#define ODIM  128
#define BM    64
#define HC    128
#define KT    64

// fp16 staged copies
__device__ __half g_xh [BATCH * NSEQ * DIM];   // [b][n][d]
__device__ __half g_w1t[NEXP * HID * DIM];     // [e][h][d]  (N-major for GEMM1 B)
__device__ __half g_w2t[NEXP * ODIM * HID];    // [e][o][h]  (N-major for GEMM2 B)

// ---- SMEM layout (bytes) ----
#define XROW 144
#define HROW 272
#define XSB  (64 * XROW)
#define WSB  (128 * XROW)
#define N_STG 3
#define XS_OFF 0
#define WS_OFF (N_STG * XSB)
#define HS_OFF (WS_OFF + N_STG * WSB)
#define SMEM_BYTES (HS_OFF + BM * HROW + 64)   // 100416

__device__ __forceinline__ uint32_t smem_u32(const void* p) {
    uint32_t a;
    asm("{ .reg .u64 t; cvta.to.shared.u64 t, %1; cvt.u32.u64 %0, t; }" : "=r"(a) : "l"(p));
    return a;
}

#define CP16(dst, src) \
    asm volatile("cp.async.cg.shared.global [%0], [%1], 16;" :: "r"(dst), "l"(src) : "memory")
#define CP_COMMIT() asm volatile("cp.async.commit_group;" ::: "memory")
#define CP_WAIT(n)  asm volatile("cp.async.wait_group %0;" :: "n"(n) : "memory")

__device__ __forceinline__ void ldsm4(uint32_t& r0, uint32_t& r1, uint32_t& r2, uint32_t& r3,
                                      uint32_t addr) {
    asm volatile("ldmatrix.sync.aligned.m8n8.x4.shared.b16 {%0,%1,%2,%3}, [%4];"
        : "=r"(r0), "=r"(r1), "=r"(r2), "=r"(r3) : "r"(addr));
}

// fp16-accumulator MMA: d,c are 2x b32 (f16x2); chains in f16
__device__ __forceinline__ void mma_f16acc(uint32_t c[2], const uint32_t a[4],
                                           uint32_t b0, uint32_t b1) {
    asm volatile(
        "mma.sync.aligned.m16n8k16.row.col.f16.f16.f16.f16 "
        "{%0,%1}, {%2,%3,%4,%5}, {%6,%7}, {%0,%1};"
        : "+r"(c[0]), "+r"(c[1])
        : "r"(a[0]), "r"(a[1]), "r"(a[2]), "r"(a[3]), "r"(b0), "r"(b1));
}

__device__ __forceinline__ void ld_frag(uint32_t* A, uint32_t* B,
                                        uint32_t abase, uint32_t astr,
                                        uint32_t bbase, uint32_t bstr) {
    ldsm4(A[0], A[1], A[2], A[3], abase);
    ldsm4(A[4], A[5], A[6], A[7], abase + astr);
    ldsm4(B[0], B[1], B[2], B[3], bbase);
    ldsm4(B[4], B[5], B[6], B[7], bbase + bstr);
}

// 8 MMAs (2 m16 x 4 n8) into f16 accumulators
__device__ __forceinline__ void exec_frag16(uint32_t acc[2][4][2],
                                            const uint32_t* A, const uint32_t* B) {
    mma_f16acc(acc[0][0], A,     B[0], B[1]);
    mma_f16acc(acc[0][1], A,     B[2], B[3]);
    mma_f16acc(acc[0][2], A,     B[4], B[5]);
    mma_f16acc(acc[0][3], A,     B[6], B[7]);
    mma_f16acc(acc[1][0], A + 4, B[0], B[1]);
    mma_f16acc(acc[1][1], A + 4, B[2], B[3]);
    mma_f16acc(acc[1][2], A + 4, B[4], B[5]);
    mma_f16acc(acc[1][3], A + 4, B[6], B[7]);
}

// promote f16 partial sums into fp32 accumulators, zero the f16 bank
__device__ __forceinline__ void promote(float a32[2][4][4], uint32_t a16[2][4][2]) {
    #pragma unroll
    for (int mt = 0; mt < 2; mt++)
        #pragma unroll
        for (int ot = 0; ot < 4; ot++) {
            float2 lo = __half22float2(*(__half2*)&a16[mt][ot][0]);
            float2 hi = __half22float2(*(__half2*)&a16[mt][ot][1]);
            a32[mt][ot][0] += lo.x;
            a32[mt][ot][1] += lo.y;
            a32[mt][ot][2] += hi.x;
            a32[mt][ot][3] += hi.y;
            a16[mt][ot][0] = 0u;
            a16[mt][ot][1] = 0u;
        }
}

__device__ __forceinline__ float gelu_exact(float v) {
    return 0.5f * v * (1.0f + erff(v * 0.70710678118654752440f));
}

// ---------------- prep kernels ----------------
__global__ void prep_x(const float* __restrict__ src, int n4) {
    int i = blockIdx.x * blockDim.x + threadIdx.x;
    if (i < n4) {
        float4 v = ((const float4*)src)[i];
        ((__half2*)g_xh)[i * 2]     = __floats2half2_rn(v.x, v.y);
        ((__half2*)g_xh)[i * 2 + 1] = __floats2half2_rn(v.z, v.w);
    }
}

__global__ void prep_w1t(const float* __restrict__ w1) {
    __shared__ float t[32][33];
    int d0 = blockIdx.x * 32, h0 = blockIdx.y * 32, e = blockIdx.z;
    const float* src = w1 + (size_t)e * DIM * HID;
    __half*      dst = g_w1t + (size_t)e * HID * DIM;
    int tx = threadIdx.x, ty = threadIdx.y;
    #pragma unroll
    for (int k = 0; k < 4; k++)
        t[ty + k*8][tx] = src[(size_t)(d0 + ty + k*8) * HID + h0 + tx];
    __syncthreads();
    #pragma unroll
    for (int k = 0; k < 4; k++)
        dst[(size_t)(h0 + ty + k*8) * DIM + d0 + tx] = __float2half_rn(t[tx][ty + k*8]);
}

__global__ void prep_w2t(const float* __restrict__ w2) {
    __shared__ float t[32][33];
    int h0 = blockIdx.x * 32, o0 = blockIdx.y * 32, e = blockIdx.z;
    const float* src = w2 + (size_t)e * HID * ODIM;
    __half*      dst = g_w2t + (size_t)e * ODIM * HID;
    int tx = threadIdx.x, ty = threadIdx.y;
    #pragma unroll
    for (int k = 0; k < 4; k++)
        t[ty + k*8][tx] = src[(size_t)(h0 + ty + k*8) * ODIM + o0 + tx];
    __syncthreads();
    #pragma unroll
    for (int k = 0; k < 4; k++)
        dst[(size_t)(o0 + ty + k*8) * HID + h0 + tx] = __float2half_rn(t[tx][ty + k*8]);
}

// ---------------- main fused kernel ----------------
extern __shared__ char smem[];

__global__ __launch_bounds__(256, 1)
void experts_fused_kernel(float* __restrict__ out)
{
    const uint32_t sb = smem_u32(smem);

    const int nt = blockIdx.x;   // 0..31
    const int e  = blockIdx.y;   // 0..15
    const int b  = blockIdx.z;   // 0..3
    const int n0 = nt * BM;

    const __half* xb  = g_xh  + (size_t)(b * NSEQ + n0) * DIM;
    const __half* w1e = g_w1t + (size_t)e * HID * DIM;
    const __half* w2e = g_w2t + (size_t)e * ODIM * HID;

    const int tid  = threadIdx.x;
    const int warp = tid >> 5;
    const int lane = tid & 31;
    const int g    = lane >> 2;
    const int tig  = lane & 3;
    const int wm   = warp >> 2;   // 0..1
    const int wn   = warp & 3;    // 0..3
    const int m0w  = wm * 32;
    const int n0w  = wn * 32;

    // cp.async coords
    const int cr0 = tid >> 3;          // base row (0..31)
    const int cc0 = (tid & 7) << 4;    // byte col
    const int cs0 = (tid & 7) << 3;    // half col

    const uint32_t xa_off = (uint32_t)((m0w + (lane & 15)) * XROW + (lane >> 4) * 16);
    const uint32_t wb_off = (uint32_t)((n0w + (lane & 7) + ((lane >> 4) & 1) * 8) * XROW
                                       + ((lane >> 3) & 1) * 16);
    const uint32_t ha_off = (uint32_t)(HS_OFF + (m0w + (lane & 15)) * HROW + (lane >> 4) * 16);

    #define LOADX(t, s) do {                                                           \
        uint32_t xd = sb + XS_OFF + (s)*XSB;                                           \
        CP16(xd + (cr0)      * XROW + cc0, xb + (size_t)(cr0)      * DIM + (t)*KT + cs0); \
        CP16(xd + (cr0 + 32) * XROW + cc0, xb + (size_t)(cr0 + 32) * DIM + (t)*KT + cs0); \
    } while (0)
    #define LOADW1(t, hcI, s) do {                                                     \
        uint32_t wd = sb + WS_OFF + (s)*WSB;                                           \
        CP16(wd + (cr0)      * XROW + cc0, w1e + (size_t)((hcI)*HC + cr0)      * DIM + (t)*KT + cs0); \
        CP16(wd + (cr0 + 32) * XROW + cc0, w1e + (size_t)((hcI)*HC + cr0 + 32) * DIM + (t)*KT + cs0); \
        CP16(wd + (cr0 + 64) * XROW + cc0, w1e + (size_t)((hcI)*HC + cr0 + 64) * DIM + (t)*KT + cs0); \
        CP16(wd + (cr0 + 96) * XROW + cc0, w1e + (size_t)((hcI)*HC + cr0 + 96) * DIM + (t)*KT + cs0); \
    } while (0)
    #define LOADW2(t, hcI, s) do {                                                     \
        uint32_t wd = sb + WS_OFF + (s)*WSB;                                           \
        CP16(wd + (cr0)      * XROW + cc0, w2e + (size_t)(cr0)      * HID + (hcI)*HC + (t)*KT + cs0); \
        CP16(wd + (cr0 + 32) * XROW + cc0, w2e + (size_t)(cr0 + 32) * HID + (hcI)*HC + (t)*KT + cs0); \
        CP16(wd + (cr0 + 64) * XROW + cc0, w2e + (size_t)(cr0 + 64) * HID + (hcI)*HC + (t)*KT + cs0); \
        CP16(wd + (cr0 + 96) * XROW + cc0, w2e + (size_t)(cr0 + 96) * HID + (hcI)*HC + (t)*KT + cs0); \
    } while (0)

    // ping-pong fragment sets + shared f16 accumulator bank
    uint32_t aP[8], bP[8];
    uint32_t aQ[8], bQ[8];
    uint32_t a16[2][4][2];
    #pragma unroll
    for (int mt = 0; mt < 2; mt++)
        #pragma unroll
        for (int ot = 0; ot < 4; ot++) { a16[mt][ot][0] = 0u; a16[mt][ot][1] = 0u; }

    float oacc[2][4][4];
    #pragma unroll
    for (int mt = 0; mt < 2; mt++)
        #pragma unroll
        for (int ot = 0; ot < 4; ot++)
            #pragma unroll
            for (int i = 0; i < 4; i++) oacc[mt][ot][i] = 0.0f;

    for (int hcI = 0; hcI < HID / HC; hcI++) {
        // ========== Phase A: hidden[64,128] = X @ W1chunk, 8 k64-iters ==========
        float hacc[2][4][4];
        #pragma unroll
        for (int mt = 0; mt < 2; mt++)
            #pragma unroll
            for (int ot = 0; ot < 4; ot++)
                #pragma unroll
                for (int i = 0; i < 4; i++) hacc[mt][ot][i] = 0.0f;

        LOADX(0, 0); LOADW1(0, hcI, 0); CP_COMMIT();
        LOADX(1, 1); LOADW1(1, hcI, 1); CP_COMMIT();

        for (int t = 0; t < 8; t++) {
            const int s = t % N_STG;
            if (t < 7) { CP_WAIT(1); } else { CP_WAIT(0); }
            __syncthreads();
            const uint32_t xa = sb + XS_OFF + s * XSB + xa_off;
            const uint32_t wa = sb + WS_OFF + s * WSB + wb_off;

            ld_frag(aP, bP, xa, 16*XROW, wa, 16*XROW);
            if (t + 2 < 8) {
                const int s2 = (t + 2) % N_STG;
                LOADX(t + 2, s2); LOADW1(t + 2, hcI, s2); CP_COMMIT();
            }
            // k64 chained in f16 accumulators (4 steps), then promote to fp32
            ld_frag(aQ, bQ, xa + 32, 16*XROW, wa + 32, 16*XROW);
            exec_frag16(a16, aP, bP);
            ld_frag(aP, bP, xa + 64, 16*XROW, wa + 64, 16*XROW);
            exec_frag16(a16, aQ, bQ);
            ld_frag(aQ, bQ, xa + 96, 16*XROW, wa + 96, 16*XROW);
            exec_frag16(a16, aP, bP);
            exec_frag16(a16, aQ, bQ);
            promote(hacc, a16);
        }
        __syncthreads();   // phase-A reads done; ws/hs free to overwrite

        LOADW2(0, hcI, 0); CP_COMMIT();
        LOADW2(1, hcI, 1); CP_COMMIT();

        // ========== GELU: hacc -> hs (fp16) ==========
        #pragma unroll
        for (int mt = 0; mt < 2; mt++) {
            #pragma unroll
            for (int ot = 0; ot < 4; ot++) {
                int r0 = m0w + mt * 16 + g;
                int c  = n0w + ot * 8 + 2 * tig;
                __half2 lo = __floats2half2_rn(gelu_exact(hacc[mt][ot][0]),
                                               gelu_exact(hacc[mt][ot][1]));
                __half2 hi = __floats2half2_rn(gelu_exact(hacc[mt][ot][2]),
                                               gelu_exact(hacc[mt][ot][3]));
                *(__half2*)(smem + HS_OFF + r0 * HROW + c * 2)       = lo;
                *(__half2*)(smem + HS_OFF + (r0 + 8) * HROW + c * 2) = hi;
            }
        }
        CP_WAIT(0);
        __syncthreads();

        // ========== Phase B: out += gelu(hidden) @ W2chunk (2 k64 tiles) ==========
        for (int t2 = 0; t2 < 2; t2++) {
            const uint32_t ha = sb + ha_off + t2 * 128;
            const uint32_t wa = sb + WS_OFF + t2 * WSB + wb_off;
            ld_frag(aP, bP, ha,      16*HROW, wa,      16*XROW);
            ld_frag(aQ, bQ, ha + 32, 16*HROW, wa + 32, 16*XROW);
            exec_frag16(a16, aP, bP);
            ld_frag(aP, bP, ha + 64, 16*HROW, wa + 64, 16*XROW);
            exec_frag16(a16, aQ, bQ);
            ld_frag(aQ, bQ, ha + 96, 16*HROW, wa + 96, 16*XROW);
            exec_frag16(a16, aP, bP);
            exec_frag16(a16, aQ, bQ);
            promote(oacc, a16);    // fp32 promote per k64 tile
        }
        __syncthreads();
    }

    // ========== Epilogue: out[b][n][o][e], e innermost ==========
    #pragma unroll
    for (int mt = 0; mt < 2; mt++) {
        #pragma unroll
        for (int ot = 0; ot < 4; ot++) {
            int n_row = n0 + m0w + mt * 16 + g;
            int ocol  = n0w + ot * 8 + 2 * tig;
            size_t base = (((size_t)b * NSEQ + n_row) * ODIM + ocol) * NEXP + e;
            out[base]                                  = oacc[mt][ot][0];
            out[base + NEXP]                           = oacc[mt][ot][1];
            out[base + (size_t)8 * ODIM * NEXP]        = oacc[mt][ot][2];
            out[base + (size_t)8 * ODIM * NEXP + NEXP] = oacc[mt][ot][3];
        }
    }
}

// ---------------- launch ----------------
extern "C" void kernel_launch(void* const* d_in, const int* in_sizes, int n_in,
                              void* d_out, int out_size) {
    const float* x  = (const float*)d_in[0];
    const float* w1 = (const float*)d_in[1];
    const float* w2 = (const float*)d_in[2];
    float* out = (float*)d_out;
    (void)in_sizes; (void)n_in; (void)out_size;

    cudaFuncSetAttribute(experts_fused_kernel,
                         cudaFuncAttributeMaxDynamicSharedMemorySize, SMEM_BYTES);
    cudaFuncSetAttribute(experts_fused_kernel,
                         cudaFuncAttributePreferredSharedMemoryCarveout, 100);

    const int nx = BATCH * NSEQ * DIM / 4;
    prep_x<<<(nx + 255) / 256, 256>>>(x, nx);
    dim3 tb(32, 8, 1);
    prep_w1t<<<dim3(DIM/32, HID/32, NEXP), tb>>>(w1);
    prep_w2t<<<dim3(HID/32, ODIM/32, NEXP), tb>>>(w2);

    dim3 grid(NSEQ / BM, NEXP, BATCH);  // (32,16,4) = 2048 CTAs
    experts_fused_kernel<<<grid, 256, SMEM_BYTES>>>(out);
}